// round 7
// baseline (speedup 1.0000x reference)
#include <cuda_runtime.h>

// Problem constants
#define NB   2
#define C    128
#define H    64
#define WID  64
#define HW   4096       // H*WID
#define KK   81         // L*L
#define PADR 4          // L/2

// Tiling for sim/weighting kernels
#define TH   4
#define TW   16
#define TP   64         // TH*TW pixels per tile
#define HY   12         // TH + 8 halo rows
#define HX   24         // TW + 8 halo cols
#define KST  28         // padded halo row stride (multiple of 4 for float4)
#define CCB  32         // channel chunk (sim kernel)
#define CCD  32         // channel chunk (weighting kernel)
#define WST  68         // padded px stride for weight smem rows

// Scratch (allocation-free rule: __device__ globals)
__device__ float g_key   [NB * C * HW];
__device__ float g_query [NB * C * HW];
__device__ float g_weight[NB * HW * KK];

// ---------------------------------------------------------------------------
// Kernel A: 1x1-conv projections.  Y[o][p] = sum_i W[o][i] * X[i][p]
// grid = (HW/64, 4): y = which*2 + n; which 0 -> key from ft, 1 -> query from fk
// ---------------------------------------------------------------------------
__global__ __launch_bounds__(256) void gemm_kernel(
        const float* __restrict__ ft, const float* __restrict__ fk,
        const float* __restrict__ Wm)
{
    __shared__ float As[8][128];   // As[kk][o] = W[o][kb+kk]
    __shared__ float Xs[8][64];

    const int t  = threadIdx.x;
    const int p0 = blockIdx.x * 64;
    const int n  = blockIdx.y & 1;
    const int which = blockIdx.y >> 1;
    const float* X = (which ? fk : ft) + n * C * HW;
    float*       Y = (which ? g_query : g_key) + n * C * HW;

    const int po4 = (t & 15) * 4;   // 4 pixels
    const int co8 = (t >> 4) * 8;   // 8 output channels
    float acc[8][4] = {};

    const int o  = t >> 1;
    const int h4 = (t & 1) * 4;

    for (int kb = 0; kb < C; kb += 8) {
        // stage W chunk (transposed) and X chunk
        float4 wv = *(const float4*)&Wm[o * C + kb + h4];
        As[h4 + 0][o] = wv.x;  As[h4 + 1][o] = wv.y;
        As[h4 + 2][o] = wv.z;  As[h4 + 3][o] = wv.w;
        if (t < 128) {
            const int kk = t >> 4;
            const int px = (t & 15) * 4;
            *(float4*)&Xs[kk][px] = *(const float4*)&X[(kb + kk) * HW + p0 + px];
        }
        __syncthreads();
        #pragma unroll
        for (int kk = 0; kk < 8; kk++) {
            float4 a0 = *(const float4*)&As[kk][co8];
            float4 a1 = *(const float4*)&As[kk][co8 + 4];
            float4 b  = *(const float4*)&Xs[kk][po4];
            const float av[8] = {a0.x, a0.y, a0.z, a0.w, a1.x, a1.y, a1.z, a1.w};
            const float bv[4] = {b.x, b.y, b.z, b.w};
            #pragma unroll
            for (int j = 0; j < 8; j++)
                #pragma unroll
                for (int p = 0; p < 4; p++)
                    acc[j][p] += av[j] * bv[p];
        }
        __syncthreads();
    }
    #pragma unroll
    for (int j = 0; j < 8; j++) {
        *(float4*)&Y[(co8 + j) * HW + p0 + po4] =
            make_float4(acc[j][0], acc[j][1], acc[j][2], acc[j][3]);
    }
}

// ---------------------------------------------------------------------------
// Kernel B: sim (query . shifted key, zero-padded) + softmax over 81 taps.
// 128 blocks (one per 4x16 pixel tile), 288 threads:
//   t -> (chalf = t/144, di = (t%144)/16, 4-pixel group = t%16)
// Channel loop chunked through smem halo tiles; each thread keeps 36
// accumulators (9 dj x 4 px) for half the channels; halves merged in smem.
// ---------------------------------------------------------------------------
__global__ __launch_bounds__(288) void sim_softmax_kernel()
{
    extern __shared__ float sm[];
    float* ks   = sm;                    // CCB*HY*KST = 10752 floats
    float* qs   = ks + CCB * HY * KST;   // CCB*TP     =  2048
    float* simb = qs + CCB * TP;         // TP*KK      =  5184

    const int t   = threadIdx.x;
    const int bx  = blockIdx.x;
    const int n   = bx >> 6;             // 64 tiles per image
    const int rem = bx & 63;
    const int ty0 = (rem >> 2) * TH;
    const int tx0 = (rem & 3) * TW;

    const float* keyg = g_key   + n * C * HW;
    const float* qg   = g_query + n * C * HW;

    const int chalf = t / 144;
    const int r     = t % 144;
    const int di    = r / 16;
    const int pxg   = r % 16;
    const int ly    = pxg >> 2;
    const int lxg   = (pxg & 3) * 4;

    float acc[9][4] = {};

    for (int cc = 0; cc < C; cc += CCB) {
        // stage key halo (zero-padded) and query tile for this channel chunk
        for (int i = t; i < CCB * HY * HX; i += 288) {
            int hx = i % HX;
            int hy = (i / HX) % HY;
            int c  = i / (HX * HY);
            int gy = ty0 + hy - PADR;
            int gx = tx0 + hx - PADR;
            float v = 0.f;
            if ((unsigned)gy < H && (unsigned)gx < WID)
                v = keyg[(cc + c) * HW + gy * WID + gx];
            ks[c * (HY * KST) + hy * KST + hx] = v;
        }
        for (int i = t; i < CCB * TP; i += 288) {
            int px = i % TP;
            int c  = i / TP;
            qs[c * TP + px] =
                qg[(cc + c) * HW + (ty0 + (px >> 4)) * WID + tx0 + (px & 15)];
        }
        __syncthreads();

        const int cbeg = chalf * 16;
        #pragma unroll 2
        for (int c = cbeg; c < cbeg + 16; c++) {
            float4 q4 = *(const float4*)&qs[c * TP + ly * TW + lxg];
            const float* kp = &ks[c * (HY * KST) + (ly + di) * KST + lxg];
            float4 k0 = *(const float4*)kp;
            float4 k1 = *(const float4*)(kp + 4);
            float4 k2 = *(const float4*)(kp + 8);
            const float qv[4]  = {q4.x, q4.y, q4.z, q4.w};
            const float kr[12] = {k0.x, k0.y, k0.z, k0.w,
                                  k1.x, k1.y, k1.z, k1.w,
                                  k2.x, k2.y, k2.z, k2.w};
            #pragma unroll
            for (int dj = 0; dj < 9; dj++)
                #pragma unroll
                for (int p = 0; p < 4; p++)
                    acc[dj][p] += qv[p] * kr[dj + p];
        }
        __syncthreads();
    }

    // merge the two channel halves into smem sim
    const int pxb = ly * TW + lxg;
    if (chalf == 0) {
        #pragma unroll
        for (int dj = 0; dj < 9; dj++)
            #pragma unroll
            for (int p = 0; p < 4; p++)
                simb[(pxb + p) * KK + di * 9 + dj] = acc[dj][p];
    }
    __syncthreads();
    if (chalf == 1) {
        #pragma unroll
        for (int dj = 0; dj < 9; dj++)
            #pragma unroll
            for (int p = 0; p < 4; p++)
                simb[(pxb + p) * KK + di * 9 + dj] += acc[dj][p];
    }
    __syncthreads();

    // softmax over 81 taps: 4 lanes per pixel, butterfly reduce
    if (t < 256) {
        const int px = t >> 2;
        const int q  = t & 3;
        float* srow = &simb[px * KK];
        float m = -1e30f;
        for (int k = q; k < KK; k += 4) m = fmaxf(m, srow[k]);
        m = fmaxf(m, __shfl_xor_sync(0xffffffffu, m, 1));
        m = fmaxf(m, __shfl_xor_sync(0xffffffffu, m, 2));
        float s = 0.f;
        for (int k = q; k < KK; k += 4) {
            float e = __expf(srow[k] - m);
            srow[k] = e;
            s += e;
        }
        s += __shfl_xor_sync(0xffffffffu, s, 1);
        s += __shfl_xor_sync(0xffffffffu, s, 2);
        const float inv = 1.f / s;
        float* wout = &g_weight[((n * H + ty0 + (px >> 4)) * WID + tx0 + (px & 15)) * KK];
        for (int k = q; k < KK; k += 4) wout[k] = srow[k] * inv;
    }
}

// ---------------------------------------------------------------------------
// Kernel D: out[c][p] = sum_k weight[p][k] * ft[c][p + off_k]  (zero-padded)
// grid = (128 tiles, 4 channel chunks), 256 threads:
//   t -> (channel pair = t/16, 4-pixel group = t%16)
// weight tile staged in smem as [k][px] so the weight load is one float4
// shared (deduped) across the channel-pair register block.
// ---------------------------------------------------------------------------
__global__ __launch_bounds__(256) void weight_kernel(
        const float* __restrict__ ft, float* __restrict__ out)
{
    extern __shared__ float sm[];
    float* fts = sm;                    // CCD*HY*KST = 10752 floats
    float* ws  = fts + CCD * HY * KST;  // KK*WST     =  5508

    const int t   = threadIdx.x;
    const int bx  = blockIdx.x;
    const int n   = bx >> 6;
    const int rem = bx & 63;
    const int ty0 = (rem >> 2) * TH;
    const int tx0 = (rem & 3) * TW;
    const int c0  = blockIdx.y * CCD;
    const float* ftn = ft + n * C * HW;

    for (int i = t; i < TP * KK; i += 256) {
        int k  = i % KK;
        int px = i / KK;
        ws[k * WST + px] =
            g_weight[((n * H + ty0 + (px >> 4)) * WID + tx0 + (px & 15)) * KK + k];
    }
    for (int i = t; i < CCD * HY * HX; i += 256) {
        int hx = i % HX;
        int hy = (i / HX) % HY;
        int c  = i / (HX * HY);
        int gy = ty0 + hy - PADR;
        int gx = tx0 + hx - PADR;
        float v = 0.f;
        if ((unsigned)gy < H && (unsigned)gx < WID)
            v = ftn[(c0 + c) * HW + gy * WID + gx];
        fts[c * (HY * KST) + hy * KST + hx] = v;
    }
    __syncthreads();

    const int pxg = t & 15;
    const int cl  = (t >> 4) * 2;
    const int ly  = pxg >> 2;
    const int lxg = (pxg & 3) * 4;
    float a0[4] = {}, a1[4] = {};

    #pragma unroll
    for (int di = 0; di < 9; di++) {
        const float* f0 = &fts[cl * (HY * KST) + (ly + di) * KST + lxg];
        const float* f1 = f0 + HY * KST;
        float4 x0 = *(const float4*)f0;
        float4 x1 = *(const float4*)(f0 + 4);
        float4 x2 = *(const float4*)(f0 + 8);
        float4 y0 = *(const float4*)f1;
        float4 y1 = *(const float4*)(f1 + 4);
        float4 y2 = *(const float4*)(f1 + 8);
        const float fr0[12] = {x0.x, x0.y, x0.z, x0.w, x1.x, x1.y, x1.z, x1.w,
                               x2.x, x2.y, x2.z, x2.w};
        const float fr1[12] = {y0.x, y0.y, y0.z, y0.w, y1.x, y1.y, y1.z, y1.w,
                               y2.x, y2.y, y2.z, y2.w};
        #pragma unroll
        for (int dj = 0; dj < 9; dj++) {
            float4 w4 = *(const float4*)&ws[(di * 9 + dj) * WST + ly * TW + lxg];
            const float wv[4] = {w4.x, w4.y, w4.z, w4.w};
            #pragma unroll
            for (int p = 0; p < 4; p++) {
                a0[p] += wv[p] * fr0[dj + p];
                a1[p] += wv[p] * fr1[dj + p];
            }
        }
    }

    float* on = out + n * C * HW;
    const int pix = (ty0 + ly) * WID + tx0 + lxg;
    *(float4*)&on[(c0 + cl)     * HW + pix] = make_float4(a0[0], a0[1], a0[2], a0[3]);
    *(float4*)&on[(c0 + cl + 1) * HW + pix] = make_float4(a1[0], a1[1], a1[2], a1[3]);
}

// ---------------------------------------------------------------------------
extern "C" void kernel_launch(void* const* d_in, const int* in_sizes, int n_in,
                              void* d_out, int out_size)
{
    const float* ft = (const float*)d_in[0];
    const float* fk = (const float*)d_in[1];
    const float* Wm = (const float*)d_in[2];
    float* out = (float*)d_out;

    const int smB = (CCB * HY * KST + CCB * TP + TP * KK) * (int)sizeof(float); // 71936
    const int smD = (CCD * HY * KST + KK * WST) * (int)sizeof(float);           // 65040
    cudaFuncSetAttribute(sim_softmax_kernel,
                         cudaFuncAttributeMaxDynamicSharedMemorySize, smB);
    cudaFuncSetAttribute(weight_kernel,
                         cudaFuncAttributeMaxDynamicSharedMemorySize, smD);

    gemm_kernel<<<dim3(HW / 64, 4), 256>>>(ft, fk, Wm);
    sim_softmax_kernel<<<NB * (H / TH) * (WID / TW), 288, smB>>>();
    weight_kernel<<<dim3(NB * (H / TH) * (WID / TW), C / CCD), 256, smD>>>(ft, out);
}

// round 8
// speedup vs baseline: 1.8300x; 1.8300x over previous
#include <cuda_runtime.h>

// Problem constants
#define NB   2
#define C    128
#define H    64
#define WID  64
#define HW   4096       // H*WID
#define KK   81         // L*L
#define PADR 4          // L/2

// sim kernel tiling (2x16 px tiles -> 256 blocks)
#define BTH  2
#define BTW  16
#define BTP  32         // px per tile
#define BHY  10         // 2 + 8 halo rows
#define BHX  24
#define BKST 28         // padded halo row stride
#define CCB  32         // channel chunk

// weighting kernel tiling (4x16 px tiles x 4 channel chunks -> 512 blocks)
#define TH   4
#define TW   16
#define TP   64
#define HY   12
#define HX   24
#define KST  28
#define CCD  32
#define WST  68

#define GK   16         // gemm W k-chunk

// Scratch (allocation-free rule: __device__ globals)
__device__ float g_key   [NB * C * HW];
__device__ float g_query [NB * C * HW];
__device__ float g_weight[NB * HW * KK];

// ---- packed fp32x2 helpers (sm_100+: ptxas never emits FFMA2 from C++) ----
typedef unsigned long long u64;
__device__ __forceinline__ u64 pk(float lo, float hi) {
    u64 r; asm("mov.b64 %0, {%1, %2};" : "=l"(r) : "f"(lo), "f"(hi)); return r;
}
__device__ __forceinline__ void fma2(u64& d, u64 a, u64 b) {
    asm("fma.rn.f32x2 %0, %1, %2, %0;" : "+l"(d) : "l"(a), "l"(b));
}
__device__ __forceinline__ float2 upk(u64 v) {
    float2 r; asm("mov.b64 {%0, %1}, %2;" : "=f"(r.x), "=f"(r.y) : "l"(v)); return r;
}

// ---------------------------------------------------------------------------
// Kernel A: 1x1-conv projections.  Y[o][p] = sum_i W[o][i] * X[i][p]
// grid = (64, 4). Full X tile (128c x 64px = 32KB) resident in smem; W staged
// in double-buffered 16-k chunks (1 sync per 16 k). FFMA2 over o-pairs.
// ---------------------------------------------------------------------------
__global__ __launch_bounds__(256) void gemm_kernel(
        const float* __restrict__ ft, const float* __restrict__ fk,
        const float* __restrict__ Wm)
{
    extern __shared__ float sm[];
    float* Xs = sm;                 // [128][64]
    float* Ws = sm + 128 * 64;      // [2][GK][128]

    const int t  = threadIdx.x;
    const int p0 = blockIdx.x * 64;
    const int n  = blockIdx.y & 1;
    const int which = blockIdx.y >> 1;
    const float* X = (which ? fk : ft) + n * C * HW;
    float*       Y = (which ? g_query : g_key) + n * C * HW;

    const int px  = (t & 15) * 4;
    const int co8 = (t >> 4) * 8;

    // load full X tile
    {
        const int cc = t >> 4;
        const int xp = (t & 15) * 4;
        #pragma unroll
        for (int it = 0; it < 8; it++) {
            int c = cc + it * 16;
            *(float4*)&Xs[c * 64 + xp] = *(const float4*)&X[c * HW + p0 + xp];
        }
    }
    // stage W chunk kb (transposed: Ws[buf][kk][o])
    const int so  = t >> 1;          // 0..127 : o row
    const int sk4 = (t & 1) * 8;     // handles kk sk4..sk4+7 via 2 float4
    // (each thread stages 2 float4 of its o row per chunk)
    auto stageW = [&](int buf, int kb) {
        float* Wb = Ws + buf * (GK * 128);
        #pragma unroll
        for (int j = 0; j < 2; j++) {
            int k4 = sk4 + j * 4;
            float4 wv = *(const float4*)&Wm[so * C + kb + k4];
            Wb[(k4 + 0) * 128 + so] = wv.x;
            Wb[(k4 + 1) * 128 + so] = wv.y;
            Wb[(k4 + 2) * 128 + so] = wv.z;
            Wb[(k4 + 3) * 128 + so] = wv.w;
        }
    };
    stageW(0, 0);

    u64 acc[4][4] = {};   // [o-pair][px]
    __syncthreads();

    int buf = 0;
    for (int kb = 0; kb < 8; kb++) {
        if (kb < 7) stageW(buf ^ 1, (kb + 1) * GK);
        const float* Wb = Ws + buf * (GK * 128);
        const float* Xb = Xs + (kb * GK) * 64;
        #pragma unroll
        for (int kk = 0; kk < GK; kk++) {
            float4 a0 = *(const float4*)&Wb[kk * 128 + co8];
            float4 a1 = *(const float4*)&Wb[kk * 128 + co8 + 4];
            float4 b  = *(const float4*)&Xb[kk * 64 + px];
            u64 ap0 = pk(a0.x, a0.y), ap1 = pk(a0.z, a0.w);
            u64 ap2 = pk(a1.x, a1.y), ap3 = pk(a1.z, a1.w);
            u64 b0 = pk(b.x, b.x), b1 = pk(b.y, b.y);
            u64 b2 = pk(b.z, b.z), b3 = pk(b.w, b.w);
            fma2(acc[0][0], ap0, b0); fma2(acc[0][1], ap0, b1);
            fma2(acc[0][2], ap0, b2); fma2(acc[0][3], ap0, b3);
            fma2(acc[1][0], ap1, b0); fma2(acc[1][1], ap1, b1);
            fma2(acc[1][2], ap1, b2); fma2(acc[1][3], ap1, b3);
            fma2(acc[2][0], ap2, b0); fma2(acc[2][1], ap2, b1);
            fma2(acc[2][2], ap2, b2); fma2(acc[2][3], ap2, b3);
            fma2(acc[3][0], ap3, b0); fma2(acc[3][1], ap3, b1);
            fma2(acc[3][2], ap3, b2); fma2(acc[3][3], ap3, b3);
        }
        __syncthreads();
        buf ^= 1;
    }

    #pragma unroll
    for (int j2 = 0; j2 < 4; j2++) {
        float2 v0 = upk(acc[j2][0]), v1 = upk(acc[j2][1]);
        float2 v2 = upk(acc[j2][2]), v3 = upk(acc[j2][3]);
        *(float4*)&Y[(co8 + 2 * j2)     * HW + p0 + px] =
            make_float4(v0.x, v1.x, v2.x, v3.x);
        *(float4*)&Y[(co8 + 2 * j2 + 1) * HW + p0 + px] =
            make_float4(v0.y, v1.y, v2.y, v3.y);
    }
}

// ---------------------------------------------------------------------------
// Kernel B: sim (query . shifted key, zero-padded) + softmax over 81 taps.
// 256 blocks (2x16 px tiles), 288 threads:
//   t -> (cquart = t/72, di = (t%72)/8, px-group = t%8)
// Each c-quarter accumulates 8 channels of each 32-channel chunk; partials
// merged in 3 deterministic smem rounds. FFMA2 over px pairs.
// ---------------------------------------------------------------------------
__global__ __launch_bounds__(288) void sim_softmax_kernel()
{
    extern __shared__ float sm[];
    float* ks   = sm;                      // CCB*BHY*BKST = 8960 floats
    float* qs   = ks + CCB * BHY * BKST;   // CCB*BTP      = 1024
    float* simb = qs + CCB * BTP;          // BTP*KK       = 2592

    const int t   = threadIdx.x;
    const int bx  = blockIdx.x;
    const int n   = bx >> 7;              // 128 tiles per image
    const int rem = bx & 127;
    const int ty0 = (rem >> 2) * BTH;
    const int tx0 = (rem & 3) * BTW;

    const float* keyg = g_key   + n * C * HW;
    const float* qg   = g_query + n * C * HW;

    const int cq  = t / 72;
    const int r   = t % 72;
    const int di  = r / 8;
    const int pxg = r % 8;
    const int ly  = pxg >> 2;             // 0..1
    const int lxg = (pxg & 3) * 4;

    u64 accp[9][2] = {};                  // [dj][px-pair]

    for (int cc = 0; cc < C; cc += CCB) {
        for (int i = t; i < CCB * BHY * BHX; i += 288) {
            int hx = i % BHX;
            int hy = (i / BHX) % BHY;
            int c  = i / (BHX * BHY);
            int gy = ty0 + hy - PADR;
            int gx = tx0 + hx - PADR;
            float v = 0.f;
            if ((unsigned)gy < H && (unsigned)gx < WID)
                v = keyg[(cc + c) * HW + gy * WID + gx];
            ks[c * (BHY * BKST) + hy * BKST + hx] = v;
        }
        for (int i = t; i < CCB * BTP; i += 288) {
            int px = i % BTP;
            int c  = i / BTP;
            qs[c * BTP + px] =
                qg[(cc + c) * HW + (ty0 + (px >> 4)) * WID + tx0 + (px & 15)];
        }
        __syncthreads();

        const int cbeg = cq * 8;
        #pragma unroll 2
        for (int c = cbeg; c < cbeg + 8; c++) {
            float4 q4 = *(const float4*)&qs[c * BTP + ly * BTW + lxg];
            const float* kp = &ks[c * (BHY * BKST) + (ly + di) * BKST + lxg];
            float4 k0 = *(const float4*)kp;
            float4 k1 = *(const float4*)(kp + 4);
            float4 k2 = *(const float4*)(kp + 8);
            const float kr[12] = {k0.x, k0.y, k0.z, k0.w,
                                  k1.x, k1.y, k1.z, k1.w,
                                  k2.x, k2.y, k2.z, k2.w};
            u64 q01 = pk(q4.x, q4.y), q23 = pk(q4.z, q4.w);
            u64 win[11];
            #pragma unroll
            for (int m = 0; m < 11; m++) win[m] = pk(kr[m], kr[m + 1]);
            #pragma unroll
            for (int dj = 0; dj < 9; dj++) {
                fma2(accp[dj][0], q01, win[dj]);
                fma2(accp[dj][1], q23, win[dj + 2]);
            }
        }
        __syncthreads();
    }

    // merge 4 channel quarters into smem sim (deterministic rounds)
    const int pxb = ly * BTW + lxg;
    if (cq == 0) {
        #pragma unroll
        for (int dj = 0; dj < 9; dj++) {
            float2 v0 = upk(accp[dj][0]), v1 = upk(accp[dj][1]);
            simb[(pxb + 0) * KK + di * 9 + dj] = v0.x;
            simb[(pxb + 1) * KK + di * 9 + dj] = v0.y;
            simb[(pxb + 2) * KK + di * 9 + dj] = v1.x;
            simb[(pxb + 3) * KK + di * 9 + dj] = v1.y;
        }
    }
    __syncthreads();
    #pragma unroll
    for (int rr = 1; rr < 4; rr++) {
        if (cq == rr) {
            #pragma unroll
            for (int dj = 0; dj < 9; dj++) {
                float2 v0 = upk(accp[dj][0]), v1 = upk(accp[dj][1]);
                simb[(pxb + 0) * KK + di * 9 + dj] += v0.x;
                simb[(pxb + 1) * KK + di * 9 + dj] += v0.y;
                simb[(pxb + 2) * KK + di * 9 + dj] += v1.x;
                simb[(pxb + 3) * KK + di * 9 + dj] += v1.y;
            }
        }
        __syncthreads();
    }

    // softmax over 81 taps: 8 lanes per pixel, butterfly reduce
    if (t < 256) {
        const int px = t >> 3;
        const int q  = t & 7;
        float* srow = &simb[px * KK];
        float m = -1e30f;
        for (int k = q; k < KK; k += 8) m = fmaxf(m, srow[k]);
        m = fmaxf(m, __shfl_xor_sync(0xffffffffu, m, 1));
        m = fmaxf(m, __shfl_xor_sync(0xffffffffu, m, 2));
        m = fmaxf(m, __shfl_xor_sync(0xffffffffu, m, 4));
        float s = 0.f;
        for (int k = q; k < KK; k += 8) {
            float e = __expf(srow[k] - m);
            srow[k] = e;
            s += e;
        }
        s += __shfl_xor_sync(0xffffffffu, s, 1);
        s += __shfl_xor_sync(0xffffffffu, s, 2);
        s += __shfl_xor_sync(0xffffffffu, s, 4);
        const float inv = 1.f / s;
        float* wout = &g_weight[((n * H + ty0 + (px >> 4)) * WID + tx0 + (px & 15)) * KK];
        for (int k = q; k < KK; k += 8) wout[k] = srow[k] * inv;
    }
}

// ---------------------------------------------------------------------------
// Kernel D: out[c][p] = sum_k weight[p][k] * ft[c][p + off_k]  (zero-padded)
// grid = (128 tiles, 4 channel chunks), 256 threads. FFMA2 over px pairs.
// ---------------------------------------------------------------------------
__global__ __launch_bounds__(256) void weight_kernel(
        const float* __restrict__ ft, float* __restrict__ out)
{
    extern __shared__ float sm[];
    float* fts = sm;                    // CCD*HY*KST = 10752 floats
    float* ws  = fts + CCD * HY * KST;  // KK*WST     =  5508

    const int t   = threadIdx.x;
    const int bx  = blockIdx.x;
    const int n   = bx >> 6;
    const int rem = bx & 63;
    const int ty0 = (rem >> 2) * TH;
    const int tx0 = (rem & 3) * TW;
    const int c0  = blockIdx.y * CCD;
    const float* ftn = ft + n * C * HW;

    for (int i = t; i < TP * KK; i += 256) {
        int k  = i % KK;
        int px = i / KK;
        ws[k * WST + px] =
            g_weight[((n * H + ty0 + (px >> 4)) * WID + tx0 + (px & 15)) * KK + k];
    }
    for (int i = t; i < CCD * HY * HX; i += 256) {
        int hx = i % HX;
        int hy = (i / HX) % HY;
        int c  = i / (HX * HY);
        int gy = ty0 + hy - PADR;
        int gx = tx0 + hx - PADR;
        float v = 0.f;
        if ((unsigned)gy < H && (unsigned)gx < WID)
            v = ftn[(c0 + c) * HW + gy * WID + gx];
        fts[c * (HY * KST) + hy * KST + hx] = v;
    }
    __syncthreads();

    const int pxg = t & 15;
    const int cl  = (t >> 4) * 2;
    const int ly  = pxg >> 2;
    const int lxg = (pxg & 3) * 4;
    u64 ap0[2] = {}, ap1[2] = {};       // two channels x two px pairs

    #pragma unroll
    for (int di = 0; di < 9; di++) {
        const float* f0 = &fts[cl * (HY * KST) + (ly + di) * KST + lxg];
        const float* f1 = f0 + HY * KST;
        float4 x0 = *(const float4*)f0;
        float4 x1 = *(const float4*)(f0 + 4);
        float4 x2 = *(const float4*)(f0 + 8);
        float4 y0 = *(const float4*)f1;
        float4 y1 = *(const float4*)(f1 + 4);
        float4 y2 = *(const float4*)(f1 + 8);
        const float fr0[12] = {x0.x, x0.y, x0.z, x0.w, x1.x, x1.y, x1.z, x1.w,
                               x2.x, x2.y, x2.z, x2.w};
        const float fr1[12] = {y0.x, y0.y, y0.z, y0.w, y1.x, y1.y, y1.z, y1.w,
                               y2.x, y2.y, y2.z, y2.w};
        u64 w0[11], w1[11];
        #pragma unroll
        for (int m = 0; m < 11; m++) {
            w0[m] = pk(fr0[m], fr0[m + 1]);
            w1[m] = pk(fr1[m], fr1[m + 1]);
        }
        #pragma unroll
        for (int dj = 0; dj < 9; dj++) {
            float4 w4 = *(const float4*)&ws[(di * 9 + dj) * WST + ly * TW + lxg];
            u64 w01 = pk(w4.x, w4.y), w23 = pk(w4.z, w4.w);
            fma2(ap0[0], w01, w0[dj]);
            fma2(ap0[1], w23, w0[dj + 2]);
            fma2(ap1[0], w01, w1[dj]);
            fma2(ap1[1], w23, w1[dj + 2]);
        }
    }

    float* on = out + n * C * HW;
    const int pix = (ty0 + ly) * WID + tx0 + lxg;
    {
        float2 v0 = upk(ap0[0]), v1 = upk(ap0[1]);
        *(float4*)&on[(c0 + cl) * HW + pix] = make_float4(v0.x, v0.y, v1.x, v1.y);
    }
    {
        float2 v0 = upk(ap1[0]), v1 = upk(ap1[1]);
        *(float4*)&on[(c0 + cl + 1) * HW + pix] = make_float4(v0.x, v0.y, v1.x, v1.y);
    }
}

// ---------------------------------------------------------------------------
extern "C" void kernel_launch(void* const* d_in, const int* in_sizes, int n_in,
                              void* d_out, int out_size)
{
    const float* ft = (const float*)d_in[0];
    const float* fk = (const float*)d_in[1];
    const float* Wm = (const float*)d_in[2];
    float* out = (float*)d_out;

    const int smA = (128 * 64 + 2 * GK * 128) * (int)sizeof(float);            // 49152
    const int smB = (CCB * BHY * BKST + CCB * BTP + BTP * KK) * (int)sizeof(float); // 50304
    const int smD = (CCD * HY * KST + KK * WST) * (int)sizeof(float);          // 65040
    cudaFuncSetAttribute(gemm_kernel,
                         cudaFuncAttributeMaxDynamicSharedMemorySize, smA);
    cudaFuncSetAttribute(sim_softmax_kernel,
                         cudaFuncAttributeMaxDynamicSharedMemorySize, smB);
    cudaFuncSetAttribute(weight_kernel,
                         cudaFuncAttributeMaxDynamicSharedMemorySize, smD);

    gemm_kernel<<<dim3(HW / 64, 4), 256, smA>>>(ft, fk, Wm);
    sim_softmax_kernel<<<NB * (H / BTH) * (WID / BTW), 288, smB>>>();
    weight_kernel<<<dim3(NB * (H / TH) * (WID / TW), C / CCD), 256, smD>>>(ft, out);
}